// round 13
// baseline (speedup 1.0000x reference)
#include <cuda_runtime.h>
#include <cuda_fp16.h>
#include <cstdint>

#define N_TOK 16384
#define D_IN  1024
#define D_OUT 1024
#define N_EXP 8

#define BM 128
#define BN 128
#define KC 32                     // k per stage (fp16: 64B per row)
#define ROWB 80                   // padded smem row bytes: conflict-free LDSM
#define TILEB (BM * ROWB)         // 10240 per operand tile
#define STAGEB (2 * TILEB)        // A + B = 20480
#define NSTAGE 3
#define SMEM_TOTAL (NSTAGE * STAGEB)   // 61440 (2 CTAs/SM -> 120KB)
#define KITER (D_IN / KC)              // 32
#define NITER (N_EXP * KITER)          // 256
#define NOBLK (D_OUT / BN)             // 8 o-tiles per m-tile
#define NMBLK (N_TOK / BM)             // 128 m-tiles

// ---------------- scratch ----------------
__device__ float  g_probs[N_TOK * N_EXP];
__device__ float  g_cvec[N_EXP * D_OUT];
__device__ __half g_embs_h[(size_t)N_TOK * D_IN];
__device__ __half g_W_h[(size_t)N_EXP * D_OUT * D_IN];
__device__ int    g_cnt[NMBLK];

// ---------------- ptx helpers ----------------
__device__ __forceinline__ uint32_t smem_u32(const void* p) {
    uint32_t a;
    asm("{ .reg .u64 t; cvta.to.shared.u64 t, %1; cvt.u32.u64 %0, t; }" : "=r"(a) : "l"(p));
    return a;
}

__device__ __forceinline__ void cp16(uint32_t dst, const void* src) {
    asm volatile("cp.async.cg.shared.global [%0], [%1], 16;" :: "r"(dst), "l"(src));
}
__device__ __forceinline__ void cp_commit() {
    asm volatile("cp.async.commit_group;");
}
template <int N>
__device__ __forceinline__ void cp_wait() {
    asm volatile("cp.async.wait_group %0;" :: "n"(N));
}

__device__ __forceinline__ void ldsm4(uint32_t& r0, uint32_t& r1, uint32_t& r2,
                                      uint32_t& r3, uint32_t addr) {
    asm volatile("ldmatrix.sync.aligned.m8n8.x4.shared.b16 {%0,%1,%2,%3}, [%4];"
                 : "=r"(r0), "=r"(r1), "=r"(r2), "=r"(r3) : "r"(addr));
}

__device__ __forceinline__ void mma_f16(float d[4], const uint32_t a[4],
                                        uint32_t b0, uint32_t b1) {
    asm volatile(
        "mma.sync.aligned.m16n8k16.row.col.f32.f16.f16.f32 "
        "{%0,%1,%2,%3}, {%4,%5,%6,%7}, {%8,%9}, {%0,%1,%2,%3};\n"
        : "+f"(d[0]), "+f"(d[1]), "+f"(d[2]), "+f"(d[3])
        : "r"(a[0]), "r"(a[1]), "r"(a[2]), "r"(a[3]), "r"(b0), "r"(b1));
}

// ---------------- fused prep: gating (blocks 0..2047) + cvec (blocks 2048..3071) ----------------
__global__ void prep_kernel(const float* __restrict__ embs,
                            const float* __restrict__ expsT,
                            const float* __restrict__ bias,
                            const float* __restrict__ W) {
    const int bid  = blockIdx.x;
    const int tid  = threadIdx.x;
    const int lane = tid & 31;

    if (bid < 2048) {
        // ---- gating: one warp per token; softmax + embs->fp16 ----
        int gw = (bid * 256 + tid) >> 5;
        const float* row = embs + (size_t)gw * D_IN;
        __half* hrow = g_embs_h + (size_t)gw * D_IN;
        float acc[8];
#pragma unroll
        for (int e = 0; e < 8; e++) acc[e] = 0.f;
        for (int d = lane; d < D_IN; d += 32) {
            float x = row[d];
            hrow[d] = __float2half_rn(x);
            const float4* wp = reinterpret_cast<const float4*>(expsT + d * 8);
            float4 w0 = wp[0], w1 = wp[1];
            acc[0] += x * w0.x; acc[1] += x * w0.y; acc[2] += x * w0.z; acc[3] += x * w0.w;
            acc[4] += x * w1.x; acc[5] += x * w1.y; acc[6] += x * w1.z; acc[7] += x * w1.w;
        }
#pragma unroll
        for (int off = 16; off > 0; off >>= 1)
#pragma unroll
            for (int e = 0; e < 8; e++)
                acc[e] += __shfl_xor_sync(0xffffffffu, acc[e], off);
        if (lane == 0) {
            float m = acc[0];
#pragma unroll
            for (int e = 1; e < 8; e++) m = fmaxf(m, acc[e]);
            float ex[8]; float s = 0.f;
#pragma unroll
            for (int e = 0; e < 8; e++) { ex[e] = __expf(acc[e] - m); s += ex[e]; }
            float inv = 1.f / s;
#pragma unroll
            for (int e = 0; e < 8; e++) g_probs[gw * 8 + e] = ex[e] * inv;
        }
    } else {
        // ---- cvec: one warp per (e,o); c = bias[e].W[e,o,:]; W->fp16 ----
        if (bid == 2048 && tid < NMBLK) g_cnt[tid] = 0;   // reset per replay
        int gw = ((bid - 2048) * 256 + tid) >> 5;         // 0..8191
        int e = gw >> 10;
        const float4* bp = reinterpret_cast<const float4*>(bias + (size_t)e * D_IN);
        const float4* wp = reinterpret_cast<const float4*>(W + ((size_t)gw << 10));
        __half2* hp = reinterpret_cast<__half2*>(g_W_h + ((size_t)gw << 10));
        float s = 0.f;
        for (int i = lane; i < D_IN / 4; i += 32) {
            float4 b = bp[i], w = wp[i];
            hp[i * 2 + 0] = __floats2half2_rn(w.x, w.y);
            hp[i * 2 + 1] = __floats2half2_rn(w.z, w.w);
            s += b.x * w.x + b.y * w.y + b.z * w.z + b.w * w.w;
        }
#pragma unroll
        for (int off = 16; off > 0; off >>= 1)
            s += __shfl_xor_sync(0xffffffffu, s, off);
        if (lane == 0) g_cvec[gw] = s;
    }
}

// ---------------- main kernel: fp16 MMA + inline tail multi ----------------
__global__ __launch_bounds__(256, 2)
void moe_main_kernel(float* __restrict__ out_exp, float* __restrict__ out_multi) {
    extern __shared__ __align__(128) char sm[];
    const uint32_t sb = smem_u32(sm);
    __shared__ int s_won;

    const int tid  = threadIdx.x;
    const int lane = tid & 31;
    const int warp = tid >> 5;
    const int wm   = warp >> 1;   // 0..3
    const int wn   = warp & 1;    // 0..1
    const int g    = lane >> 2;
    const int t    = lane & 3;

    const int o0 = blockIdx.x * BN;
    const int m0 = blockIdx.y * BM;

    // cp.async task mapping: 2 chunks of A + 2 of B per thread
    const int arow0 = tid >> 1;
    const int achk0 = (tid & 1) * 2;
    const __half* a_src0 = g_embs_h + (size_t)(m0 + arow0) * D_IN + achk0 * 8;
    const __half* b_srcB = g_W_h + (size_t)(o0 + arow0) * D_IN + achk0 * 8;
    const uint32_t a_dst0 = sb + arow0 * ROWB + achk0 * 16;
    const uint32_t b_dst0 = sb + TILEB + arow0 * ROWB + achk0 * 16;

    // ldmatrix lane offsets
    const uint32_t aLane = (lane & 15) * ROWB + (lane >> 4) * 16;
    const uint32_t bLane = ((lane & 7) + ((lane >> 4) << 3)) * ROWB + ((lane >> 3) & 1) * 16;

    // prologue: issue stages for iters 0 and 1
#pragma unroll
    for (int p = 0; p < 2; p++) {
        const uint32_t soff = p * STAGEB;
        const __half* as = a_src0 + p * KC;
        const __half* bs = b_srcB + p * KC;   // expert 0
#pragma unroll
        for (int i = 0; i < 2; i++) {
            cp16(a_dst0 + soff + i * 16, as + i * 8);
            cp16(b_dst0 + soff + i * 16, bs + i * 8);
        }
        cp_commit();
    }

    for (int e = 0; e < N_EXP; e++) {
        float acc[2][8][4];
#pragma unroll
        for (int mi = 0; mi < 2; mi++)
#pragma unroll
            for (int ni = 0; ni < 8; ni++)
#pragma unroll
                for (int j = 0; j < 4; j++) acc[mi][ni][j] = 0.f;

#pragma unroll 1
        for (int kk0 = 0; kk0 < KITER; kk0++) {
            const int it = e * KITER + kk0;
            cp_wait<1>();          // stage `it` arrived (this thread's view)
            __syncthreads();       // all warps see it; stage (it-1) fully consumed

            // prefetch iter it+2 into the just-freed buffer
            const int it2 = it + 2;
            if (it2 < NITER) {
                const int e2 = it2 >> 5;
                const int k2 = (it2 & 31) * KC;
                const uint32_t soff = (uint32_t)(it2 % NSTAGE) * STAGEB;
                const __half* as = a_src0 + k2;
                const __half* bs = b_srcB + ((size_t)e2 << 20) + k2;
#pragma unroll
                for (int i = 0; i < 2; i++) {
                    cp16(a_dst0 + soff + i * 16, as + i * 8);
                    cp16(b_dst0 + soff + i * 16, bs + i * 8);
                }
            }
            cp_commit();   // always commit: keeps wait_group accounting exact

            const uint32_t abase = sb + (uint32_t)(it % NSTAGE) * STAGEB;
            const uint32_t bbase = abase + TILEB;

#pragma unroll
            for (int sl = 0; sl < 2; sl++) {       // two k16 slices
                const uint32_t koff = sl * 32;
                uint32_t af[2][4];
#pragma unroll
                for (int mi = 0; mi < 2; mi++)
                    ldsm4(af[mi][0], af[mi][1], af[mi][2], af[mi][3],
                          abase + (wm * 32 + mi * 16) * ROWB + koff + aLane);
#pragma unroll
                for (int nb = 0; nb < 4; nb++) {
                    uint32_t b0, b1, b2, b3;
                    ldsm4(b0, b1, b2, b3,
                          bbase + (wn * 64 + nb * 16) * ROWB + koff + bLane);
                    mma_f16(acc[0][nb * 2 + 0], af[0], b0, b1);
                    mma_f16(acc[1][nb * 2 + 0], af[1], b0, b1);
                    mma_f16(acc[0][nb * 2 + 1], af[0], b2, b3);
                    mma_f16(acc[1][nb * 2 + 1], af[1], b2, b3);
                }
            }
        }

        // epilogue for expert e: subtract c_e, store expert output
        const float* ce = g_cvec + e * D_OUT + o0;
#pragma unroll
        for (int mi = 0; mi < 2; mi++) {
            const int r0 = m0 + wm * 32 + mi * 16 + g;
#pragma unroll
            for (int ni = 0; ni < 8; ni++) {
                const int col = wn * 64 + ni * 8 + 2 * t;
                const float c0 = ce[col], c1 = ce[col + 1];
                const size_t b0i = ((size_t)r0 * N_EXP + e) * D_OUT + o0 + col;
                const size_t b1i = ((size_t)(r0 + 8) * N_EXP + e) * D_OUT + o0 + col;
                __stcs(reinterpret_cast<float2*>(out_exp + b0i),
                       make_float2(acc[mi][ni][0] - c0, acc[mi][ni][1] - c1));
                __stcs(reinterpret_cast<float2*>(out_exp + b1i),
                       make_float2(acc[mi][ni][2] - c0, acc[mi][ni][3] - c1));
            }
        }
    }

    // ---- inline multi: 8th finisher of this m-tile reduces its 128 rows ----
    __threadfence();
    __syncthreads();
    if (tid == 0)
        s_won = (atomicAdd(&g_cnt[blockIdx.y], 1) == NOBLK - 1);
    __syncthreads();
    if (s_won) {
        const float4* probs4 = reinterpret_cast<const float4*>(g_probs);
#pragma unroll 1
        for (int r = 0; r < BM; r++) {
            const int row = m0 + r;
            const float4 pa = __ldg(probs4 + row * 2);
            const float4 pb = __ldg(probs4 + row * 2 + 1);
            const float p[8] = {pa.x, pa.y, pa.z, pa.w, pb.x, pb.y, pb.z, pb.w};
            const float4* src = reinterpret_cast<const float4*>(out_exp)
                                + (size_t)row * 8 * 256 + tid;
            float4 a = make_float4(0.f, 0.f, 0.f, 0.f);
#pragma unroll
            for (int e = 0; e < 8; e++) {
                const float4 v = __ldcg(src + e * 256);
                a.x += p[e] * v.x; a.y += p[e] * v.y;
                a.z += p[e] * v.z; a.w += p[e] * v.w;
            }
            __stcs(reinterpret_cast<float4*>(out_multi) + (size_t)row * 256 + tid, a);
        }
    }
}

extern "C" void kernel_launch(void* const* d_in, const int* in_sizes, int n_in,
                              void* d_out, int out_size) {
    (void)in_sizes; (void)n_in; (void)out_size;
    const float* embs  = (const float*)d_in[0];
    const float* expsT = (const float*)d_in[1];
    const float* bias  = (const float*)d_in[2];
    const float* W     = (const float*)d_in[3];

    float* out       = (float*)d_out;
    float* out_multi = out;                           // [16384, 1024]
    float* out_exp   = out + (size_t)N_TOK * D_OUT;   // [16384, 8, 1024]

    static bool attr_set = false;
    if (!attr_set) {
        cudaFuncSetAttribute(moe_main_kernel,
                             cudaFuncAttributeMaxDynamicSharedMemorySize, SMEM_TOTAL);
        attr_set = true;
    }

    prep_kernel<<<3072, 256>>>(embs, expsT, bias, W);

    dim3 grid(D_OUT / BN, N_TOK / BM);   // (8, 128) = 1024 CTAs
    moe_main_kernel<<<grid, 256, SMEM_TOTAL>>>(out_exp, out_multi);
}

// round 14
// speedup vs baseline: 1.0915x; 1.0915x over previous
#include <cuda_runtime.h>
#include <cuda_fp16.h>
#include <cstdint>

#define N_TOK 16384
#define D_IN  1024
#define D_OUT 1024
#define N_EXP 8

#define BM 128
#define BN 128
#define KC 32                     // k per stage (fp16: 64B per row)
#define ROWB 80                   // padded smem row bytes: conflict-free LDSM
#define TILEB (BM * ROWB)         // 10240 per operand tile
#define STAGEB (2 * TILEB)        // A + B = 20480
#define NSTAGE 3
#define SMEM_TOTAL (NSTAGE * STAGEB)   // 61440 (2 CTAs/SM -> 120KB)
#define KITER (D_IN / KC)              // 32
#define NITER (N_EXP * KITER)          // 256

// ---------------- scratch ----------------
__device__ float  g_probs[N_TOK * N_EXP];
__device__ float  g_cvec[N_EXP * D_OUT];
__device__ __half g_embs_h[(size_t)N_TOK * D_IN];
__device__ __half g_W_h[(size_t)N_EXP * D_OUT * D_IN];

// ---------------- ptx helpers ----------------
__device__ __forceinline__ uint32_t smem_u32(const void* p) {
    uint32_t a;
    asm("{ .reg .u64 t; cvta.to.shared.u64 t, %1; cvt.u32.u64 %0, t; }" : "=r"(a) : "l"(p));
    return a;
}

__device__ __forceinline__ void cp16(uint32_t dst, const void* src) {
    asm volatile("cp.async.cg.shared.global [%0], [%1], 16;" :: "r"(dst), "l"(src));
}
__device__ __forceinline__ void cp_commit() {
    asm volatile("cp.async.commit_group;");
}
template <int N>
__device__ __forceinline__ void cp_wait() {
    asm volatile("cp.async.wait_group %0;" :: "n"(N));
}

__device__ __forceinline__ void ldsm4(uint32_t& r0, uint32_t& r1, uint32_t& r2,
                                      uint32_t& r3, uint32_t addr) {
    asm volatile("ldmatrix.sync.aligned.m8n8.x4.shared.b16 {%0,%1,%2,%3}, [%4];"
                 : "=r"(r0), "=r"(r1), "=r"(r2), "=r"(r3) : "r"(addr));
}

__device__ __forceinline__ void mma_f16(float d[4], const uint32_t a[4],
                                        uint32_t b0, uint32_t b1) {
    asm volatile(
        "mma.sync.aligned.m16n8k16.row.col.f32.f16.f16.f32 "
        "{%0,%1,%2,%3}, {%4,%5,%6,%7}, {%8,%9}, {%0,%1,%2,%3};\n"
        : "+f"(d[0]), "+f"(d[1]), "+f"(d[2]), "+f"(d[3])
        : "r"(a[0]), "r"(a[1]), "r"(a[2]), "r"(a[3]), "r"(b0), "r"(b1));
}

// ---------------- fused prep: gating (blocks 0..2047) + cvec (blocks 2048..3071) ----------------
__global__ void prep_kernel(const float* __restrict__ embs,
                            const float* __restrict__ expsT,
                            const float* __restrict__ bias,
                            const float* __restrict__ W) {
    const int bid  = blockIdx.x;
    const int tid  = threadIdx.x;
    const int lane = tid & 31;

    if (bid < 2048) {
        // ---- gating: one warp per token; softmax + embs->fp16 ----
        int gw = (bid * 256 + tid) >> 5;
        const float* row = embs + (size_t)gw * D_IN;
        __half* hrow = g_embs_h + (size_t)gw * D_IN;
        float acc[8];
#pragma unroll
        for (int e = 0; e < 8; e++) acc[e] = 0.f;
        for (int d = lane; d < D_IN; d += 32) {
            float x = row[d];
            hrow[d] = __float2half_rn(x);
            const float4* wp = reinterpret_cast<const float4*>(expsT + d * 8);
            float4 w0 = wp[0], w1 = wp[1];
            acc[0] += x * w0.x; acc[1] += x * w0.y; acc[2] += x * w0.z; acc[3] += x * w0.w;
            acc[4] += x * w1.x; acc[5] += x * w1.y; acc[6] += x * w1.z; acc[7] += x * w1.w;
        }
#pragma unroll
        for (int off = 16; off > 0; off >>= 1)
#pragma unroll
            for (int e = 0; e < 8; e++)
                acc[e] += __shfl_xor_sync(0xffffffffu, acc[e], off);
        if (lane == 0) {
            float m = acc[0];
#pragma unroll
            for (int e = 1; e < 8; e++) m = fmaxf(m, acc[e]);
            float ex[8]; float s = 0.f;
#pragma unroll
            for (int e = 0; e < 8; e++) { ex[e] = __expf(acc[e] - m); s += ex[e]; }
            float inv = 1.f / s;
#pragma unroll
            for (int e = 0; e < 8; e++) g_probs[gw * 8 + e] = ex[e] * inv;
        }
    } else {
        // ---- cvec: one warp per (e,o); c = bias[e].W[e,o,:]; W->fp16 ----
        int gw = ((bid - 2048) * 256 + tid) >> 5;         // 0..8191
        int e = gw >> 10;
        const float4* bp = reinterpret_cast<const float4*>(bias + (size_t)e * D_IN);
        const float4* wp = reinterpret_cast<const float4*>(W + ((size_t)gw << 10));
        __half2* hp = reinterpret_cast<__half2*>(g_W_h + ((size_t)gw << 10));
        float s = 0.f;
        for (int i = lane; i < D_IN / 4; i += 32) {
            float4 b = bp[i], w = wp[i];
            hp[i * 2 + 0] = __floats2half2_rn(w.x, w.y);
            hp[i * 2 + 1] = __floats2half2_rn(w.z, w.w);
            s += b.x * w.x + b.y * w.y + b.z * w.z + b.w * w.w;
        }
#pragma unroll
        for (int off = 16; off > 0; off >>= 1)
            s += __shfl_xor_sync(0xffffffffu, s, off);
        if (lane == 0) g_cvec[gw] = s;
    }
}

// ---------------- main kernel (round-12 proven): fp16 MMA, 2 CTAs/SM ----------------
__global__ __launch_bounds__(256, 2)
void moe_main_kernel(float* __restrict__ out_exp) {
    extern __shared__ __align__(128) char sm[];
    const uint32_t sb = smem_u32(sm);

    const int tid  = threadIdx.x;
    const int lane = tid & 31;
    const int warp = tid >> 5;
    const int wm   = warp >> 1;   // 0..3
    const int wn   = warp & 1;    // 0..1
    const int g    = lane >> 2;
    const int t    = lane & 3;

    const int o0 = blockIdx.x * BN;
    const int m0 = blockIdx.y * BM;

    // cp.async task mapping: 2 chunks of A + 2 of B per thread
    const int arow0 = tid >> 1;
    const int achk0 = (tid & 1) * 2;
    const __half* a_src0 = g_embs_h + (size_t)(m0 + arow0) * D_IN + achk0 * 8;
    const __half* b_srcB = g_W_h + (size_t)(o0 + arow0) * D_IN + achk0 * 8;
    const uint32_t a_dst0 = sb + arow0 * ROWB + achk0 * 16;
    const uint32_t b_dst0 = sb + TILEB + arow0 * ROWB + achk0 * 16;

    // ldmatrix lane offsets
    const uint32_t aLane = (lane & 15) * ROWB + (lane >> 4) * 16;
    const uint32_t bLane = ((lane & 7) + ((lane >> 4) << 3)) * ROWB + ((lane >> 3) & 1) * 16;

    // prologue: issue stages for iters 0 and 1
#pragma unroll
    for (int p = 0; p < 2; p++) {
        const uint32_t soff = p * STAGEB;
        const __half* as = a_src0 + p * KC;
        const __half* bs = b_srcB + p * KC;   // expert 0
#pragma unroll
        for (int i = 0; i < 2; i++) {
            cp16(a_dst0 + soff + i * 16, as + i * 8);
            cp16(b_dst0 + soff + i * 16, bs + i * 8);
        }
        cp_commit();
    }

    for (int e = 0; e < N_EXP; e++) {
        float acc[2][8][4];
#pragma unroll
        for (int mi = 0; mi < 2; mi++)
#pragma unroll
            for (int ni = 0; ni < 8; ni++)
#pragma unroll
                for (int j = 0; j < 4; j++) acc[mi][ni][j] = 0.f;

#pragma unroll 1
        for (int kk0 = 0; kk0 < KITER; kk0++) {
            const int it = e * KITER + kk0;
            cp_wait<1>();          // stage `it` arrived (this thread's view)
            __syncthreads();       // all warps see it; stage (it-1) fully consumed

            // prefetch iter it+2 into the just-freed buffer
            const int it2 = it + 2;
            if (it2 < NITER) {
                const int e2 = it2 >> 5;
                const int k2 = (it2 & 31) * KC;
                const uint32_t soff = (uint32_t)(it2 % NSTAGE) * STAGEB;
                const __half* as = a_src0 + k2;
                const __half* bs = b_srcB + ((size_t)e2 << 20) + k2;
#pragma unroll
                for (int i = 0; i < 2; i++) {
                    cp16(a_dst0 + soff + i * 16, as + i * 8);
                    cp16(b_dst0 + soff + i * 16, bs + i * 8);
                }
            }
            cp_commit();   // always commit: keeps wait_group accounting exact

            const uint32_t abase = sb + (uint32_t)(it % NSTAGE) * STAGEB;
            const uint32_t bbase = abase + TILEB;

#pragma unroll
            for (int sl = 0; sl < 2; sl++) {       // two k16 slices
                const uint32_t koff = sl * 32;
                uint32_t af[2][4];
#pragma unroll
                for (int mi = 0; mi < 2; mi++)
                    ldsm4(af[mi][0], af[mi][1], af[mi][2], af[mi][3],
                          abase + (wm * 32 + mi * 16) * ROWB + koff + aLane);
#pragma unroll
                for (int nb = 0; nb < 4; nb++) {
                    uint32_t b0, b1, b2, b3;
                    ldsm4(b0, b1, b2, b3,
                          bbase + (wn * 64 + nb * 16) * ROWB + koff + bLane);
                    mma_f16(acc[0][nb * 2 + 0], af[0], b0, b1);
                    mma_f16(acc[1][nb * 2 + 0], af[1], b0, b1);
                    mma_f16(acc[0][nb * 2 + 1], af[0], b2, b3);
                    mma_f16(acc[1][nb * 2 + 1], af[1], b2, b3);
                }
            }
        }

        // epilogue for expert e: subtract c_e, store expert output
        const float* ce = g_cvec + e * D_OUT + o0;
#pragma unroll
        for (int mi = 0; mi < 2; mi++) {
            const int r0 = m0 + wm * 32 + mi * 16 + g;
#pragma unroll
            for (int ni = 0; ni < 8; ni++) {
                const int col = wn * 64 + ni * 8 + 2 * t;
                const float c0 = ce[col], c1 = ce[col + 1];
                const size_t b0i = ((size_t)r0 * N_EXP + e) * D_OUT + o0 + col;
                const size_t b1i = ((size_t)(r0 + 8) * N_EXP + e) * D_OUT + o0 + col;
                __stcs(reinterpret_cast<float2*>(out_exp + b0i),
                       make_float2(acc[mi][ni][0] - c0, acc[mi][ni][1] - c1));
                __stcs(reinterpret_cast<float2*>(out_exp + b1i),
                       make_float2(acc[mi][ni][2] - c0, acc[mi][ni][3] - c1));
            }
        }
    }
}

// ---------------- multi_out = sum_e p[r,e] * expert_outputs[r,e,:] (measured 80us) ----------------
__global__ __launch_bounds__(256, 4)
void multi_kernel(const float* __restrict__ out_exp, float* __restrict__ out_multi) {
    const int r   = blockIdx.x;
    const int tid = threadIdx.x;          // 256 threads, 1 float4 each
    float p8[8];
#pragma unroll
    for (int e = 0; e < 8; e++) p8[e] = g_probs[r * 8 + e];
    const float4* src = reinterpret_cast<const float4*>(out_exp) + (size_t)r * 8 * 256 + tid;
    float4 a = make_float4(0.f, 0.f, 0.f, 0.f);
#pragma unroll
    for (int e = 0; e < 8; e++) {
        float4 v = __ldcs(src + e * 256);
        a.x += p8[e] * v.x; a.y += p8[e] * v.y;
        a.z += p8[e] * v.z; a.w += p8[e] * v.w;
    }
    reinterpret_cast<float4*>(out_multi)[(size_t)r * 256 + tid] = a;
}

extern "C" void kernel_launch(void* const* d_in, const int* in_sizes, int n_in,
                              void* d_out, int out_size) {
    (void)in_sizes; (void)n_in; (void)out_size;
    const float* embs  = (const float*)d_in[0];
    const float* expsT = (const float*)d_in[1];
    const float* bias  = (const float*)d_in[2];
    const float* W     = (const float*)d_in[3];

    float* out       = (float*)d_out;
    float* out_multi = out;                           // [16384, 1024]
    float* out_exp   = out + (size_t)N_TOK * D_OUT;   // [16384, 8, 1024]

    static bool attr_set = false;
    if (!attr_set) {
        cudaFuncSetAttribute(moe_main_kernel,
                             cudaFuncAttributeMaxDynamicSharedMemorySize, SMEM_TOTAL);
        attr_set = true;
    }

    prep_kernel<<<3072, 256>>>(embs, expsT, bias, W);

    dim3 grid(D_OUT / BN, N_TOK / BM);   // (8, 128) = 1024 CTAs
    moe_main_kernel<<<grid, 256, SMEM_TOTAL>>>(out_exp);

    multi_kernel<<<N_TOK, 256>>>(out_exp, out_multi);
}

// round 15
// speedup vs baseline: 1.1225x; 1.0284x over previous
#include <cuda_runtime.h>
#include <cuda_fp16.h>
#include <cstdint>

#define N_TOK 16384
#define D_IN  1024
#define D_OUT 1024
#define N_EXP 8

#define BM 128
#define BN 128
#define KC 32                     // k per stage (fp16: 64B per row)
#define ROWB 80                   // padded smem row bytes: conflict-free LDSM
#define TILEB (BM * ROWB)         // 10240 per operand tile
#define STAGEB (2 * TILEB)        // A + B = 20480
#define NSTAGE 3
#define SMEM_TOTAL (NSTAGE * STAGEB)   // 61440 (2 CTAs/SM -> 120KB)
#define KITER (D_IN / KC)              // 32
#define NITER (N_EXP * KITER)          // 256
#define NOBLK (D_OUT / BN)             // 8 o-tiles per m-tile
#define NMBLK (N_TOK / BM)             // 128 m-tiles
#define NMAIN (NOBLK * NMBLK)          // 1024 main blocks

// ---------------- scratch ----------------
__device__ float  g_probs[N_TOK * N_EXP];
__device__ float  g_cvec[N_EXP * D_OUT];
__device__ __half g_embs_h[(size_t)N_TOK * D_IN];
__device__ __half g_W_h[(size_t)N_EXP * D_OUT * D_IN];
__device__ int    g_cnt[NMBLK];

// ---------------- ptx helpers ----------------
__device__ __forceinline__ uint32_t smem_u32(const void* p) {
    uint32_t a;
    asm("{ .reg .u64 t; cvta.to.shared.u64 t, %1; cvt.u32.u64 %0, t; }" : "=r"(a) : "l"(p));
    return a;
}

__device__ __forceinline__ void cp16(uint32_t dst, const void* src) {
    asm volatile("cp.async.cg.shared.global [%0], [%1], 16;" :: "r"(dst), "l"(src));
}
__device__ __forceinline__ void cp_commit() {
    asm volatile("cp.async.commit_group;");
}
template <int N>
__device__ __forceinline__ void cp_wait() {
    asm volatile("cp.async.wait_group %0;" :: "n"(N));
}

__device__ __forceinline__ void ldsm4(uint32_t& r0, uint32_t& r1, uint32_t& r2,
                                      uint32_t& r3, uint32_t addr) {
    asm volatile("ldmatrix.sync.aligned.m8n8.x4.shared.b16 {%0,%1,%2,%3}, [%4];"
                 : "=r"(r0), "=r"(r1), "=r"(r2), "=r"(r3) : "r"(addr));
}

__device__ __forceinline__ void mma_f16(float d[4], const uint32_t a[4],
                                        uint32_t b0, uint32_t b1) {
    asm volatile(
        "mma.sync.aligned.m16n8k16.row.col.f32.f16.f16.f32 "
        "{%0,%1,%2,%3}, {%4,%5,%6,%7}, {%8,%9}, {%0,%1,%2,%3};\n"
        : "+f"(d[0]), "+f"(d[1]), "+f"(d[2]), "+f"(d[3])
        : "r"(a[0]), "r"(a[1]), "r"(a[2]), "r"(a[3]), "r"(b0), "r"(b1));
}

// ---------------- fused prep: gating (blocks 0..2047) + cvec (blocks 2048..3071) ----------------
__global__ void prep_kernel(const float* __restrict__ embs,
                            const float* __restrict__ expsT,
                            const float* __restrict__ bias,
                            const float* __restrict__ W) {
    const int bid  = blockIdx.x;
    const int tid  = threadIdx.x;
    const int lane = tid & 31;

    if (bid < 2048) {
        // ---- gating: one warp per token; softmax + embs->fp16 ----
        int gw = (bid * 256 + tid) >> 5;
        const float* row = embs + (size_t)gw * D_IN;
        __half* hrow = g_embs_h + (size_t)gw * D_IN;
        float acc[8];
#pragma unroll
        for (int e = 0; e < 8; e++) acc[e] = 0.f;
        for (int d = lane; d < D_IN; d += 32) {
            float x = row[d];
            hrow[d] = __float2half_rn(x);
            const float4* wp = reinterpret_cast<const float4*>(expsT + d * 8);
            float4 w0 = wp[0], w1 = wp[1];
            acc[0] += x * w0.x; acc[1] += x * w0.y; acc[2] += x * w0.z; acc[3] += x * w0.w;
            acc[4] += x * w1.x; acc[5] += x * w1.y; acc[6] += x * w1.z; acc[7] += x * w1.w;
        }
#pragma unroll
        for (int off = 16; off > 0; off >>= 1)
#pragma unroll
            for (int e = 0; e < 8; e++)
                acc[e] += __shfl_xor_sync(0xffffffffu, acc[e], off);
        if (lane == 0) {
            float m = acc[0];
#pragma unroll
            for (int e = 1; e < 8; e++) m = fmaxf(m, acc[e]);
            float ex[8]; float s = 0.f;
#pragma unroll
            for (int e = 0; e < 8; e++) { ex[e] = __expf(acc[e] - m); s += ex[e]; }
            float inv = 1.f / s;
#pragma unroll
            for (int e = 0; e < 8; e++) g_probs[gw * 8 + e] = ex[e] * inv;
        }
    } else {
        // ---- cvec: one warp per (e,o); c = bias[e].W[e,o,:]; W->fp16 ----
        if (bid == 2048 && tid < NMBLK) g_cnt[tid] = 0;   // reset per replay
        int gw = ((bid - 2048) * 256 + tid) >> 5;         // 0..8191
        int e = gw >> 10;
        const float4* bp = reinterpret_cast<const float4*>(bias + (size_t)e * D_IN);
        const float4* wp = reinterpret_cast<const float4*>(W + ((size_t)gw << 10));
        __half2* hp = reinterpret_cast<__half2*>(g_W_h + ((size_t)gw << 10));
        float s = 0.f;
        for (int i = lane; i < D_IN / 4; i += 32) {
            float4 b = bp[i], w = wp[i];
            hp[i * 2 + 0] = __floats2half2_rn(w.x, w.y);
            hp[i * 2 + 1] = __floats2half2_rn(w.z, w.w);
            s += b.x * w.x + b.y * w.y + b.z * w.z + b.w * w.w;
        }
#pragma unroll
        for (int off = 16; off > 0; off >>= 1)
            s += __shfl_xor_sync(0xffffffffu, s, off);
        if (lane == 0) g_cvec[gw] = s;
    }
}

// ---------------- main kernel: 1024 GEMM blocks + 128 tail multi blocks ----------------
__global__ __launch_bounds__(256, 2)
void moe_main_kernel(float* __restrict__ out_exp, float* __restrict__ out_multi) {
    extern __shared__ __align__(128) char sm[];
    const int bid = blockIdx.x;
    const int tid = threadIdx.x;

    if (bid >= NMAIN) {
        // ---- consumer block: multi_out for m-tile (bid - NMAIN) ----
        const int my = bid - NMAIN;
        if (tid == 0) {
            int v;
            do {
                asm volatile("ld.global.acquire.gpu.b32 %0, [%1];"
                             : "=r"(v) : "l"(&g_cnt[my]) : "memory");
                if (v != NOBLK) __nanosleep(256);
            } while (v != NOBLK);
        }
        __syncthreads();
        const float4* probs4 = reinterpret_cast<const float4*>(g_probs);
#pragma unroll 1
        for (int r = 0; r < BM; r++) {
            const int row = my * BM + r;
            const float4 pa = __ldg(probs4 + row * 2);
            const float4 pb = __ldg(probs4 + row * 2 + 1);
            const float p8[8] = {pa.x, pa.y, pa.z, pa.w, pb.x, pb.y, pb.z, pb.w};
            const float4* src = reinterpret_cast<const float4*>(out_exp)
                                + (size_t)row * 8 * 256 + tid;
            float4 a = make_float4(0.f, 0.f, 0.f, 0.f);
#pragma unroll
            for (int e = 0; e < 8; e++) {
                const float4 v = __ldcg(src + e * 256);
                a.x += p8[e] * v.x; a.y += p8[e] * v.y;
                a.z += p8[e] * v.z; a.w += p8[e] * v.w;
            }
            __stcs(reinterpret_cast<float4*>(out_multi) + (size_t)row * 256 + tid, a);
        }
        return;
    }

    // ---- GEMM block ----
    const uint32_t sb = smem_u32(sm);
    const int lane = tid & 31;
    const int warp = tid >> 5;
    const int wm   = warp >> 1;   // 0..3
    const int wn   = warp & 1;    // 0..1
    const int g    = lane >> 2;
    const int t    = lane & 3;

    const int o0 = (bid & (NOBLK - 1)) * BN;
    const int my = bid >> 3;
    const int m0 = my * BM;

    // cp.async task mapping: 2 chunks of A + 2 of B per thread
    const int arow0 = tid >> 1;
    const int achk0 = (tid & 1) * 2;
    const __half* a_src0 = g_embs_h + (size_t)(m0 + arow0) * D_IN + achk0 * 8;
    const __half* b_srcB = g_W_h + (size_t)(o0 + arow0) * D_IN + achk0 * 8;
    const uint32_t a_dst0 = sb + arow0 * ROWB + achk0 * 16;
    const uint32_t b_dst0 = sb + TILEB + arow0 * ROWB + achk0 * 16;

    // ldmatrix lane offsets
    const uint32_t aLane = (lane & 15) * ROWB + (lane >> 4) * 16;
    const uint32_t bLane = ((lane & 7) + ((lane >> 4) << 3)) * ROWB + ((lane >> 3) & 1) * 16;

    // prologue: issue stages for iters 0 and 1
#pragma unroll
    for (int p = 0; p < 2; p++) {
        const uint32_t soff = p * STAGEB;
        const __half* as = a_src0 + p * KC;
        const __half* bs = b_srcB + p * KC;   // expert 0
#pragma unroll
        for (int i = 0; i < 2; i++) {
            cp16(a_dst0 + soff + i * 16, as + i * 8);
            cp16(b_dst0 + soff + i * 16, bs + i * 8);
        }
        cp_commit();
    }

    for (int e = 0; e < N_EXP; e++) {
        float acc[2][8][4];
#pragma unroll
        for (int mi = 0; mi < 2; mi++)
#pragma unroll
            for (int ni = 0; ni < 8; ni++)
#pragma unroll
                for (int j = 0; j < 4; j++) acc[mi][ni][j] = 0.f;

#pragma unroll 1
        for (int kk0 = 0; kk0 < KITER; kk0++) {
            const int it = e * KITER + kk0;
            cp_wait<1>();          // stage `it` arrived (this thread's view)
            __syncthreads();       // all warps see it; stage (it-1) fully consumed

            // prefetch iter it+2 into the just-freed buffer
            const int it2 = it + 2;
            if (it2 < NITER) {
                const int e2 = it2 >> 5;
                const int k2 = (it2 & 31) * KC;
                const uint32_t soff = (uint32_t)(it2 % NSTAGE) * STAGEB;
                const __half* as = a_src0 + k2;
                const __half* bs = b_srcB + ((size_t)e2 << 20) + k2;
#pragma unroll
                for (int i = 0; i < 2; i++) {
                    cp16(a_dst0 + soff + i * 16, as + i * 8);
                    cp16(b_dst0 + soff + i * 16, bs + i * 8);
                }
            }
            cp_commit();   // always commit: keeps wait_group accounting exact

            const uint32_t abase = sb + (uint32_t)(it % NSTAGE) * STAGEB;
            const uint32_t bbase = abase + TILEB;

#pragma unroll
            for (int sl = 0; sl < 2; sl++) {       // two k16 slices
                const uint32_t koff = sl * 32;
                uint32_t af[2][4];
#pragma unroll
                for (int mi = 0; mi < 2; mi++)
                    ldsm4(af[mi][0], af[mi][1], af[mi][2], af[mi][3],
                          abase + (wm * 32 + mi * 16) * ROWB + koff + aLane);
#pragma unroll
                for (int nb = 0; nb < 4; nb++) {
                    uint32_t b0, b1, b2, b3;
                    ldsm4(b0, b1, b2, b3,
                          bbase + (wn * 64 + nb * 16) * ROWB + koff + bLane);
                    mma_f16(acc[0][nb * 2 + 0], af[0], b0, b1);
                    mma_f16(acc[1][nb * 2 + 0], af[1], b0, b1);
                    mma_f16(acc[0][nb * 2 + 1], af[0], b2, b3);
                    mma_f16(acc[1][nb * 2 + 1], af[1], b2, b3);
                }
            }
        }

        // epilogue for expert e: subtract c_e, store expert output
        const float* ce = g_cvec + e * D_OUT + o0;
#pragma unroll
        for (int mi = 0; mi < 2; mi++) {
            const int r0 = m0 + wm * 32 + mi * 16 + g;
#pragma unroll
            for (int ni = 0; ni < 8; ni++) {
                const int col = wn * 64 + ni * 8 + 2 * t;
                const float c0 = ce[col], c1 = ce[col + 1];
                const size_t b0i = ((size_t)r0 * N_EXP + e) * D_OUT + o0 + col;
                const size_t b1i = ((size_t)(r0 + 8) * N_EXP + e) * D_OUT + o0 + col;
                __stcs(reinterpret_cast<float2*>(out_exp + b0i),
                       make_float2(acc[mi][ni][0] - c0, acc[mi][ni][1] - c1));
                __stcs(reinterpret_cast<float2*>(out_exp + b1i),
                       make_float2(acc[mi][ni][2] - c0, acc[mi][ni][3] - c1));
            }
        }
    }

    // signal: this o-tile of m-tile `my` is complete (release)
    __threadfence();
    __syncthreads();
    if (tid == 0)
        asm volatile("red.release.gpu.global.add.u32 [%0], %1;"
                     :: "l"(&g_cnt[my]), "r"(1u) : "memory");
}

extern "C" void kernel_launch(void* const* d_in, const int* in_sizes, int n_in,
                              void* d_out, int out_size) {
    (void)in_sizes; (void)n_in; (void)out_size;
    const float* embs  = (const float*)d_in[0];
    const float* expsT = (const float*)d_in[1];
    const float* bias  = (const float*)d_in[2];
    const float* W     = (const float*)d_in[3];

    float* out       = (float*)d_out;
    float* out_multi = out;                           // [16384, 1024]
    float* out_exp   = out + (size_t)N_TOK * D_OUT;   // [16384, 8, 1024]

    static bool attr_set = false;
    if (!attr_set) {
        cudaFuncSetAttribute(moe_main_kernel,
                             cudaFuncAttributeMaxDynamicSharedMemorySize, SMEM_TOTAL);
        attr_set = true;
    }

    prep_kernel<<<3072, 256>>>(embs, expsT, bias, W);

    moe_main_kernel<<<NMAIN + NMBLK, 256, SMEM_TOTAL>>>(out_exp, out_multi);
}